// round 3
// baseline (speedup 1.0000x reference)
#include <cuda_runtime.h>
#include <cstdint>
#include <cstddef>

#define HDIM   128
#define GDIM   512      // 4*H
#define BATCH  256
#define SEQ    512
#define DIN    80
#define EMB    256
#define KSMEM  96       // k-rows of W_hh^T kept in shared memory (rest in registers)

// ---------------- device scratch (no allocations allowed) ----------------
__device__ float g_G[(size_t)BATCH * SEQ * GDIM];   // 268 MB: pre-activation gates (input part)
__device__ float g_hout[(size_t)BATCH * SEQ * HDIM];// 64 MB : per-step h_out
__device__ float g_Wc[GDIM * DIN];                  // fused  W_ih @ W_in   [512][80]
__device__ float g_bc[GDIM];                        // fused  W_ih@b_in + b_ih + b_hh
__device__ float g_WT[HDIM * GDIM];                 // W_hh transposed: WT[k][j] = W_hh[j][k]

// ---------------- math helpers ----------------
__device__ __forceinline__ float sigf(float x) {
    float xc = fminf(fmaxf(x, -30.f), 30.f);
    return __fdividef(1.0f, 1.0f + __expf(-xc));
}
__device__ __forceinline__ float tanh_fast(float x) {
    float xc = fminf(fmaxf(x, -15.f), 15.f);
    float e = __expf(2.0f * xc);
    return 1.0f - __fdividef(2.0f, e + 1.0f);
}

// ---------------- kernel 0: fold W_in into W_ih, transpose W_hh ----------------
__global__ void combine_kernel(const float* __restrict__ W_in, const float* __restrict__ b_in,
                               const float* __restrict__ W_ih, const float* __restrict__ b_ih,
                               const float* __restrict__ W_hh, const float* __restrict__ b_hh) {
    __shared__ float wih[EMB];
    int j = blockIdx.x;           // 0..511
    int tid = threadIdx.x;        // 128 threads
    for (int e = tid; e < EMB; e += 128) wih[e] = W_ih[j * EMB + e];
    // transpose W_hh row j into column j of WT
    g_WT[tid * GDIM + j] = W_hh[j * HDIM + tid];
    __syncthreads();
    if (tid < DIN) {
        float s = 0.f;
        #pragma unroll 8
        for (int e = 0; e < EMB; e++) s = fmaf(wih[e], W_in[e * DIN + tid], s);
        g_Wc[j * DIN + tid] = s;
    }
    if (tid == 96) {
        float s = b_ih[j] + b_hh[j];
        #pragma unroll 8
        for (int e = 0; e < EMB; e++) s = fmaf(wih[e], b_in[e], s);
        g_bc[j] = s;
    }
}

// ---------------- kernel 1: G[m][j] = x[m][:] . Wc[j][:] + bc[j] ----------------
// M = 131072, N = 512, K = 80. BM=BN=128, 256 threads, 8x8 register tile.
__global__ void __launch_bounds__(256) gemm_kernel(const float* __restrict__ x) {
    __shared__ float As[40][132];  // x tile transposed   As[k][m']
    __shared__ float Bs[40][132];  // Wc tile transposed  Bs[k][n']
    __shared__ float bcs[128];

    int tid = threadIdx.x;
    int n0 = blockIdx.x * 128;
    int m0 = blockIdx.y * 128;
    if (tid < 128) bcs[tid] = g_bc[n0 + tid];
    int tr = tid >> 4, tc = tid & 15;

    float acc[8][8];
    #pragma unroll
    for (int i = 0; i < 8; i++)
        #pragma unroll
        for (int jj = 0; jj < 8; jj++) acc[i][jj] = 0.f;

    for (int kt = 0; kt < 2; kt++) {
        #pragma unroll
        for (int r = 0; r < 20; r++) {
            int idx = tid + r * 256;      // 0..5119
            int row = idx / 40;
            int col = idx - row * 40;
            As[col][row] = x[(size_t)(m0 + row) * DIN + kt * 40 + col];
            Bs[col][row] = g_Wc[(n0 + row) * DIN + kt * 40 + col];
        }
        __syncthreads();
        #pragma unroll 2
        for (int k = 0; k < 40; k++) {
            float4 a0 = *(const float4*)&As[k][tr * 8];
            float4 a1 = *(const float4*)&As[k][tr * 8 + 4];
            float4 b0 = *(const float4*)&Bs[k][tc * 8];
            float4 b1 = *(const float4*)&Bs[k][tc * 8 + 4];
            float av[8] = {a0.x, a0.y, a0.z, a0.w, a1.x, a1.y, a1.z, a1.w};
            float bv[8] = {b0.x, b0.y, b0.z, b0.w, b1.x, b1.y, b1.z, b1.w};
            #pragma unroll
            for (int i = 0; i < 8; i++)
                #pragma unroll
                for (int jj = 0; jj < 8; jj++)
                    acc[i][jj] = fmaf(av[i], bv[jj], acc[i][jj]);
        }
        __syncthreads();
    }

    #pragma unroll
    for (int i = 0; i < 8; i++) {
        float* orow = g_G + (size_t)(m0 + tr * 8 + i) * GDIM + n0 + tc * 8;
        float4 v0 = make_float4(acc[i][0] + bcs[tc * 8 + 0], acc[i][1] + bcs[tc * 8 + 1],
                                acc[i][2] + bcs[tc * 8 + 2], acc[i][3] + bcs[tc * 8 + 3]);
        float4 v1 = make_float4(acc[i][4] + bcs[tc * 8 + 4], acc[i][5] + bcs[tc * 8 + 5],
                                acc[i][6] + bcs[tc * 8 + 6], acc[i][7] + bcs[tc * 8 + 7]);
        *(float4*)orow = v0;
        *(float4*)(orow + 4) = v1;
    }
}

// ---------------- kernel 2: sequential LSTM recurrence + time pooling ----------------
// 128 blocks x 512 threads; block owns batch rows (2b, 2b+1) for all 512 steps.
// W_hh^T: rows [0,96) in smem, rows [96,128) register-resident per thread (column tid).
__global__ void __launch_bounds__(512, 1) lstm_kernel(const float* __restrict__ w_time) {
    extern __shared__ float smem[];
    float* gates = smem;                 // [2][512]
    float* hbuf  = smem + 1024;          // interleaved (h_b0, h_b1) pairs: 128 float2
    float* WTs   = smem + 1280;          // [KSMEM][512]

    int tid = threadIdx.x;
    int b0 = blockIdx.x * 2;

    for (int i = tid; i < KSMEM * GDIM; i += 512) WTs[i] = g_WT[i];
    float wreg[HDIM - KSMEM];
    #pragma unroll
    for (int i = 0; i < HDIM - KSMEM; i++) wreg[i] = g_WT[(KSMEM + i) * GDIM + tid];
    if (tid < 256) hbuf[tid] = 0.f;

    float wt0 = w_time[0], wt1 = w_time[1], wt2 = w_time[2];
    float cc = 0.f, hs0 = 0.f, hs1 = 0.f, cs0 = 0.f, cs1 = 0.f;
    __syncthreads();

    const float* G0 = g_G + (size_t)b0 * SEQ * GDIM + tid;
    const float* G1 = g_G + (size_t)(b0 + 1) * SEQ * GDIM + tid;
    float* hout0 = g_hout + (size_t)b0 * SEQ * HDIM;
    float* hout1 = g_hout + (size_t)(b0 + 1) * SEQ * HDIM;

    int slot = 0;
    for (int t = 0; t < SEQ; t++) {
        float gin0 = G0[(size_t)t * GDIM];
        float gin1 = G1[(size_t)t * GDIM];
        float acc0 = gin0, acc1 = gin1;
        const float4* hp4 = (const float4*)hbuf;   // hp4[k/2] = (h0[k],h1[k],h0[k+1],h1[k+1])
        #pragma unroll
        for (int k = 0; k < KSMEM; k += 2) {
            float4 h4 = hp4[k >> 1];
            float wa = WTs[k * GDIM + tid];
            float wb = WTs[(k + 1) * GDIM + tid];
            acc0 = fmaf(wa, h4.x, acc0);
            acc1 = fmaf(wa, h4.y, acc1);
            acc0 = fmaf(wb, h4.z, acc0);
            acc1 = fmaf(wb, h4.w, acc1);
        }
        #pragma unroll
        for (int i = 0; i < HDIM - KSMEM; i += 2) {
            float4 h4 = hp4[(KSMEM + i) >> 1];
            acc0 = fmaf(wreg[i], h4.x, acc0);
            acc1 = fmaf(wreg[i], h4.y, acc1);
            acc0 = fmaf(wreg[i + 1], h4.z, acc0);
            acc1 = fmaf(wreg[i + 1], h4.w, acc1);
        }
        gates[tid] = acc0;
        gates[GDIM + tid] = acc1;
        __syncthreads();

        if (tid < 256) {
            int b = tid >> 7, k = tid & 127;
            const float* gb = gates + b * GDIM;
            float ig = gb[k], fg = gb[HDIM + k], gg = gb[2 * HDIM + k], og = gb[3 * HDIM + k];
            float cn = fmaf(sigf(fg), cc, sigf(ig) * tanh_fast(gg));
            float hn = sigf(og) * tanh_fast(cn);
            float ho, co;
            if (slot == 0)      { hs0 = hn; cs0 = cn; ho = hn; co = cn; }
            else if (slot == 1) { hs1 = hn; cs1 = cn; ho = hn; co = cn; }
            else {
                ho = wt0 * hs0 + wt1 * hs1 + wt2 * hn;
                co = wt0 * cs0 + wt1 * cs1 + wt2 * cn;
            }
            cc = co;
            hbuf[2 * k + b] = ho;
            (b ? hout1 : hout0)[(size_t)t * HDIM + k] = ho;
        }
        slot = (slot == 2) ? 0 : slot + 1;
        __syncthreads();
    }
}

// ---------------- kernel 3: logits = hout @ W_br^T + b_br, then log_softmax ----------------
// one warp per (b,s) row; 8 warps per block.
__global__ void __launch_bounds__(256) logits_kernel(const float* __restrict__ W_br,
                                                     const float* __restrict__ b_br,
                                                     float* __restrict__ out) {
    __shared__ float wbr[4 * HDIM];
    __shared__ float bb[4];
    int tid = threadIdx.x;
    for (int i = tid; i < 4 * HDIM; i += 256) wbr[i] = W_br[i];
    if (tid < 4) bb[tid] = b_br[tid];
    __syncthreads();

    int warp = tid >> 5, lane = tid & 31;
    size_t row = (size_t)blockIdx.x * 8 + warp;
    const float* h = g_hout + row * HDIM;

    float p0 = 0.f, p1 = 0.f, p2 = 0.f, p3 = 0.f;
    #pragma unroll
    for (int k = lane; k < HDIM; k += 32) {
        float hv = h[k];
        p0 = fmaf(hv, wbr[k], p0);
        p1 = fmaf(hv, wbr[HDIM + k], p1);
        p2 = fmaf(hv, wbr[2 * HDIM + k], p2);
        p3 = fmaf(hv, wbr[3 * HDIM + k], p3);
    }
    #pragma unroll
    for (int off = 16; off; off >>= 1) {
        p0 += __shfl_down_sync(0xffffffffu, p0, off);
        p1 += __shfl_down_sync(0xffffffffu, p1, off);
        p2 += __shfl_down_sync(0xffffffffu, p2, off);
        p3 += __shfl_down_sync(0xffffffffu, p3, off);
    }
    if (lane == 0) {
        float x0 = p0 + bb[0], x1 = p1 + bb[1], x2 = p2 + bb[2], x3 = p3 + bb[3];
        float m = fmaxf(fmaxf(x0, x1), fmaxf(x2, x3));
        float s = __expf(x0 - m) + __expf(x1 - m) + __expf(x2 - m) + __expf(x3 - m);
        float l = __logf(s);
        float4 o = make_float4(x0 - m - l, x1 - m - l, x2 - m - l, x3 - m - l);
        *(float4*)(out + row * 4) = o;
    }
}

// ---------------- launch ----------------
extern "C" void kernel_launch(void* const* d_in, const int* in_sizes, int n_in,
                              void* d_out, int out_size) {
    const float* x      = (const float*)d_in[0];
    const float* W_in   = (const float*)d_in[1];
    const float* b_in   = (const float*)d_in[2];
    const float* W_ih   = (const float*)d_in[3];
    const float* b_ih   = (const float*)d_in[4];
    const float* W_hh   = (const float*)d_in[5];
    const float* b_hh   = (const float*)d_in[6];
    const float* w_time = (const float*)d_in[7];
    const float* W_br   = (const float*)d_in[8];
    const float* b_br   = (const float*)d_in[9];
    float* out = (float*)d_out;

    combine_kernel<<<GDIM, 128>>>(W_in, b_in, W_ih, b_ih, W_hh, b_hh);
    gemm_kernel<<<dim3(4, 1024), 256>>>(x);

    size_t shmem = (size_t)(1024 + 256 + KSMEM * GDIM) * sizeof(float);  // 201728 B
    cudaFuncSetAttribute(lstm_kernel, cudaFuncAttributeMaxDynamicSharedMemorySize, (int)shmem);
    lstm_kernel<<<BATCH / 2, 512, shmem>>>(w_time);

    logits_kernel<<<(BATCH * SEQ) / 8, 256>>>(W_br, b_br, out);
}

// round 4
// speedup vs baseline: 1.0029x; 1.0029x over previous
#include <cuda_runtime.h>
#include <cstdint>
#include <cstddef>

#define HDIM   128
#define GDIM   512      // 4*H
#define BATCH  256
#define SEQ    512
#define DIN    80
#define EMB    256
#define KSMEM  96       // k-rows of W_hh^T kept in shared memory (rest in registers)

// ---------------- device scratch (no allocations allowed) ----------------
__device__ float g_G[(size_t)BATCH * SEQ * GDIM];   // 268 MB: pre-activation gates (input part)
__device__ float g_hout[(size_t)BATCH * SEQ * HDIM];// 64 MB : per-step h_out
__device__ float g_Wc[GDIM * DIN];                  // fused  W_ih @ W_in   [512][80]
__device__ float g_bc[GDIM];                        // fused  W_ih@b_in + b_ih + b_hh
__device__ float g_WT[HDIM * GDIM];                 // W_hh transposed: WT[k][j] = W_hh[j][k]

// ---------------- math helpers ----------------
__device__ __forceinline__ float sigf(float x) {
    float xc = fminf(fmaxf(x, -30.f), 30.f);
    return __fdividef(1.0f, 1.0f + __expf(-xc));
}
__device__ __forceinline__ float tanh_fast(float x) {
    float xc = fminf(fmaxf(x, -15.f), 15.f);
    float e = __expf(2.0f * xc);
    return 1.0f - __fdividef(2.0f, e + 1.0f);
}

// ---------------- kernel 0: fold W_in into W_ih, transpose W_hh ----------------
__global__ void combine_kernel(const float* __restrict__ W_in, const float* __restrict__ b_in,
                               const float* __restrict__ W_ih, const float* __restrict__ b_ih,
                               const float* __restrict__ W_hh, const float* __restrict__ b_hh) {
    __shared__ float wih[EMB];
    int j = blockIdx.x;           // 0..511
    int tid = threadIdx.x;        // 128 threads
    for (int e = tid; e < EMB; e += 128) wih[e] = W_ih[j * EMB + e];
    // transpose W_hh row j into column j of WT
    g_WT[tid * GDIM + j] = W_hh[j * HDIM + tid];
    __syncthreads();
    if (tid < DIN) {
        float s = 0.f;
        #pragma unroll 8
        for (int e = 0; e < EMB; e++) s = fmaf(wih[e], W_in[e * DIN + tid], s);
        g_Wc[j * DIN + tid] = s;
    }
    if (tid == 96) {
        float s = b_ih[j] + b_hh[j];
        #pragma unroll 8
        for (int e = 0; e < EMB; e++) s = fmaf(wih[e], b_in[e], s);
        g_bc[j] = s;
    }
}

// ---------------- kernel 1: G[m][j] = x[m][:] . Wc[j][:] + bc[j] ----------------
// M = 131072, N = 512, K = 80. BM=BN=128, 256 threads, 8x8 register tile.
__global__ void __launch_bounds__(256) gemm_kernel(const float* __restrict__ x) {
    __shared__ float As[40][132];  // x tile transposed   As[k][m']
    __shared__ float Bs[40][132];  // Wc tile transposed  Bs[k][n']
    __shared__ float bcs[128];

    int tid = threadIdx.x;
    int n0 = blockIdx.x * 128;
    int m0 = blockIdx.y * 128;
    if (tid < 128) bcs[tid] = g_bc[n0 + tid];
    int tr = tid >> 4, tc = tid & 15;

    float acc[8][8];
    #pragma unroll
    for (int i = 0; i < 8; i++)
        #pragma unroll
        for (int jj = 0; jj < 8; jj++) acc[i][jj] = 0.f;

    for (int kt = 0; kt < 2; kt++) {
        #pragma unroll
        for (int r = 0; r < 20; r++) {
            int idx = tid + r * 256;      // 0..5119
            int row = idx / 40;
            int col = idx - row * 40;
            As[col][row] = x[(size_t)(m0 + row) * DIN + kt * 40 + col];
            Bs[col][row] = g_Wc[(n0 + row) * DIN + kt * 40 + col];
        }
        __syncthreads();
        #pragma unroll 2
        for (int k = 0; k < 40; k++) {
            float4 a0 = *(const float4*)&As[k][tr * 8];
            float4 a1 = *(const float4*)&As[k][tr * 8 + 4];
            float4 b0 = *(const float4*)&Bs[k][tc * 8];
            float4 b1 = *(const float4*)&Bs[k][tc * 8 + 4];
            float av[8] = {a0.x, a0.y, a0.z, a0.w, a1.x, a1.y, a1.z, a1.w};
            float bv[8] = {b0.x, b0.y, b0.z, b0.w, b1.x, b1.y, b1.z, b1.w};
            #pragma unroll
            for (int i = 0; i < 8; i++)
                #pragma unroll
                for (int jj = 0; jj < 8; jj++)
                    acc[i][jj] = fmaf(av[i], bv[jj], acc[i][jj]);
        }
        __syncthreads();
    }

    #pragma unroll
    for (int i = 0; i < 8; i++) {
        float* orow = g_G + (size_t)(m0 + tr * 8 + i) * GDIM + n0 + tc * 8;
        float4 v0 = make_float4(acc[i][0] + bcs[tc * 8 + 0], acc[i][1] + bcs[tc * 8 + 1],
                                acc[i][2] + bcs[tc * 8 + 2], acc[i][3] + bcs[tc * 8 + 3]);
        float4 v1 = make_float4(acc[i][4] + bcs[tc * 8 + 4], acc[i][5] + bcs[tc * 8 + 5],
                                acc[i][6] + bcs[tc * 8 + 6], acc[i][7] + bcs[tc * 8 + 7]);
        *(float4*)orow = v0;
        *(float4*)(orow + 4) = v1;
    }
}

// ---------------- kernel 2: sequential LSTM recurrence + time pooling ----------------
// 128 blocks x 512 threads; block owns batch rows (2b, 2b+1) for all 512 steps.
// W_hh^T: rows [0,96) in smem, rows [96,128) register-resident per thread (column tid).
__global__ void __launch_bounds__(512, 1) lstm_kernel(const float* __restrict__ w_time) {
    extern __shared__ float smem[];
    float* gates = smem;                 // [2][512]
    float* hbuf  = smem + 1024;          // interleaved (h_b0, h_b1) pairs: 128 float2
    float* WTs   = smem + 1280;          // [KSMEM][512]

    int tid = threadIdx.x;
    int b0 = blockIdx.x * 2;

    for (int i = tid; i < KSMEM * GDIM; i += 512) WTs[i] = g_WT[i];
    float wreg[HDIM - KSMEM];
    #pragma unroll
    for (int i = 0; i < HDIM - KSMEM; i++) wreg[i] = g_WT[(KSMEM + i) * GDIM + tid];
    if (tid < 256) hbuf[tid] = 0.f;

    float wt0 = w_time[0], wt1 = w_time[1], wt2 = w_time[2];
    float cc = 0.f, hs0 = 0.f, hs1 = 0.f, cs0 = 0.f, cs1 = 0.f;
    __syncthreads();

    const float* G0 = g_G + (size_t)b0 * SEQ * GDIM + tid;
    const float* G1 = g_G + (size_t)(b0 + 1) * SEQ * GDIM + tid;
    float* hout0 = g_hout + (size_t)b0 * SEQ * HDIM;
    float* hout1 = g_hout + (size_t)(b0 + 1) * SEQ * HDIM;

    int slot = 0;
    for (int t = 0; t < SEQ; t++) {
        float gin0 = G0[(size_t)t * GDIM];
        float gin1 = G1[(size_t)t * GDIM];
        float acc0 = gin0, acc1 = gin1;
        const float4* hp4 = (const float4*)hbuf;   // hp4[k/2] = (h0[k],h1[k],h0[k+1],h1[k+1])
        #pragma unroll
        for (int k = 0; k < KSMEM; k += 2) {
            float4 h4 = hp4[k >> 1];
            float wa = WTs[k * GDIM + tid];
            float wb = WTs[(k + 1) * GDIM + tid];
            acc0 = fmaf(wa, h4.x, acc0);
            acc1 = fmaf(wa, h4.y, acc1);
            acc0 = fmaf(wb, h4.z, acc0);
            acc1 = fmaf(wb, h4.w, acc1);
        }
        #pragma unroll
        for (int i = 0; i < HDIM - KSMEM; i += 2) {
            float4 h4 = hp4[(KSMEM + i) >> 1];
            acc0 = fmaf(wreg[i], h4.x, acc0);
            acc1 = fmaf(wreg[i], h4.y, acc1);
            acc0 = fmaf(wreg[i + 1], h4.z, acc0);
            acc1 = fmaf(wreg[i + 1], h4.w, acc1);
        }
        gates[tid] = acc0;
        gates[GDIM + tid] = acc1;
        __syncthreads();

        if (tid < 256) {
            int b = tid >> 7, k = tid & 127;
            const float* gb = gates + b * GDIM;
            float ig = gb[k], fg = gb[HDIM + k], gg = gb[2 * HDIM + k], og = gb[3 * HDIM + k];
            float cn = fmaf(sigf(fg), cc, sigf(ig) * tanh_fast(gg));
            float hn = sigf(og) * tanh_fast(cn);
            float ho, co;
            if (slot == 0)      { hs0 = hn; cs0 = cn; ho = hn; co = cn; }
            else if (slot == 1) { hs1 = hn; cs1 = cn; ho = hn; co = cn; }
            else {
                ho = wt0 * hs0 + wt1 * hs1 + wt2 * hn;
                co = wt0 * cs0 + wt1 * cs1 + wt2 * cn;
            }
            cc = co;
            hbuf[2 * k + b] = ho;
            (b ? hout1 : hout0)[(size_t)t * HDIM + k] = ho;
        }
        slot = (slot == 2) ? 0 : slot + 1;
        __syncthreads();
    }
}

// ---------------- kernel 3: logits = hout @ W_br^T + b_br, then log_softmax ----------------
// one warp per (b,s) row; 8 warps per block.
__global__ void __launch_bounds__(256) logits_kernel(const float* __restrict__ W_br,
                                                     const float* __restrict__ b_br,
                                                     float* __restrict__ out) {
    __shared__ float wbr[4 * HDIM];
    __shared__ float bb[4];
    int tid = threadIdx.x;
    for (int i = tid; i < 4 * HDIM; i += 256) wbr[i] = W_br[i];
    if (tid < 4) bb[tid] = b_br[tid];
    __syncthreads();

    int warp = tid >> 5, lane = tid & 31;
    size_t row = (size_t)blockIdx.x * 8 + warp;
    const float* h = g_hout + row * HDIM;

    float p0 = 0.f, p1 = 0.f, p2 = 0.f, p3 = 0.f;
    #pragma unroll
    for (int k = lane; k < HDIM; k += 32) {
        float hv = h[k];
        p0 = fmaf(hv, wbr[k], p0);
        p1 = fmaf(hv, wbr[HDIM + k], p1);
        p2 = fmaf(hv, wbr[2 * HDIM + k], p2);
        p3 = fmaf(hv, wbr[3 * HDIM + k], p3);
    }
    #pragma unroll
    for (int off = 16; off; off >>= 1) {
        p0 += __shfl_down_sync(0xffffffffu, p0, off);
        p1 += __shfl_down_sync(0xffffffffu, p1, off);
        p2 += __shfl_down_sync(0xffffffffu, p2, off);
        p3 += __shfl_down_sync(0xffffffffu, p3, off);
    }
    if (lane == 0) {
        float x0 = p0 + bb[0], x1 = p1 + bb[1], x2 = p2 + bb[2], x3 = p3 + bb[3];
        float m = fmaxf(fmaxf(x0, x1), fmaxf(x2, x3));
        float s = __expf(x0 - m) + __expf(x1 - m) + __expf(x2 - m) + __expf(x3 - m);
        float l = __logf(s);
        float4 o = make_float4(x0 - m - l, x1 - m - l, x2 - m - l, x3 - m - l);
        *(float4*)(out + row * 4) = o;
    }
}

// ---------------- launch ----------------
extern "C" void kernel_launch(void* const* d_in, const int* in_sizes, int n_in,
                              void* d_out, int out_size) {
    const float* x      = (const float*)d_in[0];
    const float* W_in   = (const float*)d_in[1];
    const float* b_in   = (const float*)d_in[2];
    const float* W_ih   = (const float*)d_in[3];
    const float* b_ih   = (const float*)d_in[4];
    const float* W_hh   = (const float*)d_in[5];
    const float* b_hh   = (const float*)d_in[6];
    const float* w_time = (const float*)d_in[7];
    const float* W_br   = (const float*)d_in[8];
    const float* b_br   = (const float*)d_in[9];
    float* out = (float*)d_out;

    combine_kernel<<<GDIM, 128>>>(W_in, b_in, W_ih, b_ih, W_hh, b_hh);
    gemm_kernel<<<dim3(4, 1024), 256>>>(x);

    size_t shmem = (size_t)(1024 + 256 + KSMEM * GDIM) * sizeof(float);  // 201728 B
    cudaFuncSetAttribute(lstm_kernel, cudaFuncAttributeMaxDynamicSharedMemorySize, (int)shmem);
    lstm_kernel<<<BATCH / 2, 512, shmem>>>(w_time);

    logits_kernel<<<(BATCH * SEQ) / 8, 256>>>(W_br, b_br, out);
}

// round 5
// speedup vs baseline: 1.2221x; 1.2185x over previous
#include <cuda_runtime.h>
#include <cstdint>
#include <cstddef>

#define HDIM   128
#define GDIM   512      // 4*H
#define BATCH  256
#define SEQ    512
#define DIN    80
#define EMB    256
#define KREG   80       // k-rows of W_hh^T register-resident (as 40 packed f32x2)
#define KSP    24       // remaining (128-80)/2 = 24 k-pairs in shared memory
#define WSTRIDE 25      // float2 row stride for smem weights (pad: 50 words %32 = 18 -> 2-way)

typedef unsigned long long u64;

// ---------------- device scratch (no allocations allowed) ----------------
__device__ float g_G[(size_t)BATCH * SEQ * GDIM];    // gate pre-activations (input part)
__device__ float g_hout[(size_t)BATCH * SEQ * HDIM]; // per-step h_out
__device__ float g_Wc[GDIM * DIN];                   // fused  W_ih @ W_in   [512][80]
__device__ float g_bc[GDIM];                         // fused  W_ih@b_in + b_ih + b_hh
__device__ float g_WT[HDIM * GDIM];                  // W_hh^T: WT[k][j] = W_hh[j][k]
__device__ float2 g_WTp[GDIM * KSP];                 // k-pairs (80+2p,81+2p) per column j

// ---------------- f32x2 helpers ----------------
__device__ __forceinline__ void fma2(u64& d, u64 a, u64 b) {
    asm("fma.rn.f32x2 %0, %1, %2, %0;" : "+l"(d) : "l"(a), "l"(b));
}
__device__ __forceinline__ u64 pack2(float lo, float hi) {
    u64 r; asm("mov.b64 %0, {%1, %2};" : "=l"(r) : "f"(lo), "f"(hi)); return r;
}
__device__ __forceinline__ u64 dup2(float x) {
    u64 r; asm("mov.b64 %0, {%1, %1};" : "=l"(r) : "f"(x)); return r;
}
__device__ __forceinline__ float2 unpack2(u64 v) {
    float2 r; asm("mov.b64 {%0, %1}, %2;" : "=f"(r.x), "=f"(r.y) : "l"(v)); return r;
}

// ---------------- math helpers ----------------
__device__ __forceinline__ float sigf(float x) {
    float xc = fminf(fmaxf(x, -30.f), 30.f);
    return __fdividef(1.0f, 1.0f + __expf(-xc));
}
__device__ __forceinline__ float tanh_fast(float x) {
    float xc = fminf(fmaxf(x, -15.f), 15.f);
    float e = __expf(2.0f * xc);
    return 1.0f - __fdividef(2.0f, e + 1.0f);
}

// ---------------- kernel 0: fold W_in into W_ih, transpose W_hh ----------------
__global__ void combine_kernel(const float* __restrict__ W_in, const float* __restrict__ b_in,
                               const float* __restrict__ W_ih, const float* __restrict__ b_ih,
                               const float* __restrict__ W_hh, const float* __restrict__ b_hh) {
    __shared__ float wih[EMB];
    int j = blockIdx.x;           // 0..511
    int tid = threadIdx.x;        // 128 threads
    for (int e = tid; e < EMB; e += 128) wih[e] = W_ih[j * EMB + e];
    // transpose W_hh row j into column j of WT (k-major)
    g_WT[tid * GDIM + j] = W_hh[j * HDIM + tid];
    // packed k-pairs for the smem-resident tail (k in [80,128))
    if (tid >= KREG && !(tid & 1)) {
        g_WTp[j * KSP + ((tid - KREG) >> 1)] =
            make_float2(W_hh[j * HDIM + tid], W_hh[j * HDIM + tid + 1]);
    }
    __syncthreads();
    if (tid < DIN) {
        float s = 0.f;
        #pragma unroll 8
        for (int e = 0; e < EMB; e++) s = fmaf(wih[e], W_in[e * DIN + tid], s);
        g_Wc[j * DIN + tid] = s;
    }
    if (tid == 96) {
        float s = b_ih[j] + b_hh[j];
        #pragma unroll 8
        for (int e = 0; e < EMB; e++) s = fmaf(wih[e], b_in[e], s);
        g_bc[j] = s;
    }
}

// ---------------- kernel 1: G[m][j] = x[m][:] . Wc[j][:] + bc[j] ----------------
// M = 131072, N = 512, K = 80. BM=BN=128, 256 threads, 8x8 tile, f32x2 packed.
__global__ void __launch_bounds__(256, 2) gemm_kernel(const float* __restrict__ x) {
    __shared__ float As[40][132];  // x tile transposed   As[k][m']
    __shared__ float Bs[40][132];  // Wc tile transposed  Bs[k][n']
    __shared__ float bcs[128];

    int tid = threadIdx.x;
    int n0 = blockIdx.x * 128;
    int m0 = blockIdx.y * 128;
    if (tid < 128) bcs[tid] = g_bc[n0 + tid];
    int tr = tid >> 4, tc = tid & 15;

    u64 acc[8][4];
    #pragma unroll
    for (int i = 0; i < 8; i++)
        #pragma unroll
        for (int j = 0; j < 4; j++) acc[i][j] = 0ull;

    for (int kt = 0; kt < 2; kt++) {
        #pragma unroll
        for (int r = 0; r < 20; r++) {
            int idx = tid + r * 256;      // 0..5119
            int row = idx / 40;
            int col = idx - row * 40;
            As[col][row] = x[(size_t)(m0 + row) * DIN + kt * 40 + col];
            Bs[col][row] = g_Wc[(n0 + row) * DIN + kt * 40 + col];
        }
        __syncthreads();
        #pragma unroll 4
        for (int k = 0; k < 40; k++) {
            float4 a0 = *(const float4*)&As[k][tr * 8];
            float4 a1 = *(const float4*)&As[k][tr * 8 + 4];
            float4 b0 = *(const float4*)&Bs[k][tc * 8];
            float4 b1 = *(const float4*)&Bs[k][tc * 8 + 4];
            u64 ap[8] = {dup2(a0.x), dup2(a0.y), dup2(a0.z), dup2(a0.w),
                         dup2(a1.x), dup2(a1.y), dup2(a1.z), dup2(a1.w)};
            u64 bp[4] = {pack2(b0.x, b0.y), pack2(b0.z, b0.w),
                         pack2(b1.x, b1.y), pack2(b1.z, b1.w)};
            #pragma unroll
            for (int i = 0; i < 8; i++)
                #pragma unroll
                for (int j = 0; j < 4; j++)
                    fma2(acc[i][j], ap[i], bp[j]);
        }
        __syncthreads();
    }

    float bc0 = bcs[tc * 8 + 0], bc1 = bcs[tc * 8 + 1], bc2 = bcs[tc * 8 + 2], bc3 = bcs[tc * 8 + 3];
    float bc4 = bcs[tc * 8 + 4], bc5 = bcs[tc * 8 + 5], bc6 = bcs[tc * 8 + 6], bc7 = bcs[tc * 8 + 7];
    #pragma unroll
    for (int i = 0; i < 8; i++) {
        float* orow = g_G + (size_t)(m0 + tr * 8 + i) * GDIM + n0 + tc * 8;
        float2 v0 = unpack2(acc[i][0]), v1 = unpack2(acc[i][1]);
        float2 v2 = unpack2(acc[i][2]), v3 = unpack2(acc[i][3]);
        *(float4*)orow       = make_float4(v0.x + bc0, v0.y + bc1, v1.x + bc2, v1.y + bc3);
        *(float4*)(orow + 4) = make_float4(v2.x + bc4, v2.y + bc5, v3.x + bc6, v3.y + bc7);
    }
}

// ---------------- kernel 2: sequential LSTM recurrence + time pooling ----------------
// 128 blocks x 512 threads; block owns batch rows (2b, 2b+1) for all 512 steps.
// W^T column tid: k in [0,80) as 40 packed f32x2 registers, k in [80,128) as
// 24 packed float2 in smem (padded stride 25 -> 2-way-optimal LDS.64).
// Gate dot products run fully in fma.rn.f32x2 over k-pairs; h pairs come free
// from LDS.128 of per-batch h arrays. G for t+1 is prefetched during step t.
__global__ void __launch_bounds__(512, 1) lstm_kernel(const float* __restrict__ w_time) {
    extern __shared__ float smem[];
    float* gates = smem;                       // [2][512]
    float* hb0   = smem + 1024;                // [128] batch row 0 h
    float* hb1   = smem + 1152;                // [128] batch row 1 h
    float2* Wsp  = (float2*)(smem + 1280);     // [512][25] packed weight k-pairs

    int tid = threadIdx.x;
    int b0 = blockIdx.x * 2;

    // stage smem weights (packed pairs, padded rows)
    for (int i = tid; i < GDIM * KSP; i += 512) {
        int j = i / KSP, p = i - j * KSP;
        Wsp[j * WSTRIDE + p] = g_WTp[i];
    }
    // register weights: 40 packed pairs covering k in [0,80)
    u64 wreg[KREG / 2];
    #pragma unroll
    for (int p = 0; p < KREG / 2; p++)
        wreg[p] = pack2(g_WT[(2 * p) * GDIM + tid], g_WT[(2 * p + 1) * GDIM + tid]);

    if (tid < 128) { hb0[tid] = 0.f; hb1[tid] = 0.f; }

    float wt0 = w_time[0], wt1 = w_time[1], wt2 = w_time[2];
    float cc = 0.f, hs0 = 0.f, hs1 = 0.f, cs0 = 0.f, cs1 = 0.f;
    __syncthreads();

    const float* G0 = g_G + (size_t)b0 * SEQ * GDIM + tid;
    const float* G1 = g_G + (size_t)(b0 + 1) * SEQ * GDIM + tid;
    float* hout0 = g_hout + (size_t)b0 * SEQ * HDIM;
    float* hout1 = g_hout + (size_t)(b0 + 1) * SEQ * HDIM;

    const u64* Wrow = (const u64*)(Wsp + tid * WSTRIDE);

    float pre0 = G0[0];
    float pre1 = G1[0];

    int slot = 0;
    for (int t = 0; t < SEQ; t++) {
        u64 acc0 = pack2(pre0, 0.f);
        u64 acc1 = pack2(pre1, 0.f);
        int tn = (t + 1 < SEQ) ? (t + 1) : t;      // prefetch next step's G
        pre0 = G0[(size_t)tn * GDIM];
        pre1 = G1[(size_t)tn * GDIM];

        const ulonglong2* H0 = (const ulonglong2*)hb0;
        const ulonglong2* H1 = (const ulonglong2*)hb1;
        #pragma unroll
        for (int q = 0; q < 32; q++) {             // 4 k per q (2 pairs)
            ulonglong2 h0 = H0[q];
            ulonglong2 h1 = H1[q];
            u64 wA, wB;
            if (q < 20) { wA = wreg[2 * q]; wB = wreg[2 * q + 1]; }
            else        { wA = Wrow[2 * q - 40]; wB = Wrow[2 * q - 39]; }
            fma2(acc0, wA, h0.x);
            fma2(acc1, wA, h1.x);
            fma2(acc0, wB, h0.y);
            fma2(acc1, wB, h1.y);
        }
        float2 a0 = unpack2(acc0), a1 = unpack2(acc1);
        gates[tid]        = a0.x + a0.y;
        gates[GDIM + tid] = a1.x + a1.y;
        __syncthreads();

        if (tid < 256) {
            int b = tid >> 7, k = tid & 127;
            const float* gb = gates + b * GDIM;
            float ig = gb[k], fg = gb[HDIM + k], gg = gb[2 * HDIM + k], og = gb[3 * HDIM + k];
            float cn = fmaf(sigf(fg), cc, sigf(ig) * tanh_fast(gg));
            float hn = sigf(og) * tanh_fast(cn);
            float ho, co;
            if (slot == 0)      { hs0 = hn; cs0 = cn; ho = hn; co = cn; }
            else if (slot == 1) { hs1 = hn; cs1 = cn; ho = hn; co = cn; }
            else {
                ho = wt0 * hs0 + wt1 * hs1 + wt2 * hn;
                co = wt0 * cs0 + wt1 * cs1 + wt2 * cn;
            }
            cc = co;
            (b ? hb1 : hb0)[k] = ho;
            (b ? hout1 : hout0)[(size_t)t * HDIM + k] = ho;
        }
        slot = (slot == 2) ? 0 : slot + 1;
        __syncthreads();
    }
}

// ---------------- kernel 3: logits = hout @ W_br^T + b_br, then log_softmax ----------------
// one warp per (b,s) row; each lane owns 4 h values via a single LDG.128.
__global__ void __launch_bounds__(256) logits_kernel(const float* __restrict__ W_br,
                                                     const float* __restrict__ b_br,
                                                     float* __restrict__ out) {
    __shared__ float wbr[4 * HDIM];
    __shared__ float bb[4];
    int tid = threadIdx.x;
    for (int i = tid; i < 4 * HDIM; i += 256) wbr[i] = W_br[i];
    if (tid < 4) bb[tid] = b_br[tid];
    __syncthreads();

    int warp = tid >> 5, lane = tid & 31;
    size_t row = (size_t)blockIdx.x * 8 + warp;
    float4 hv = *(const float4*)(g_hout + row * HDIM + lane * 4);

    float p[4];
    #pragma unroll
    for (int o = 0; o < 4; o++) {
        float4 w = *(const float4*)&wbr[o * HDIM + lane * 4];
        p[o] = fmaf(hv.x, w.x, fmaf(hv.y, w.y, fmaf(hv.z, w.z, hv.w * w.w)));
    }
    #pragma unroll
    for (int off = 16; off; off >>= 1) {
        #pragma unroll
        for (int o = 0; o < 4; o++) p[o] += __shfl_xor_sync(0xffffffffu, p[o], off);
    }
    if (lane == 0) {
        float x0 = p[0] + bb[0], x1 = p[1] + bb[1], x2 = p[2] + bb[2], x3 = p[3] + bb[3];
        float m = fmaxf(fmaxf(x0, x1), fmaxf(x2, x3));
        float s = __expf(x0 - m) + __expf(x1 - m) + __expf(x2 - m) + __expf(x3 - m);
        float l = __logf(s);
        *(float4*)(out + row * 4) = make_float4(x0 - m - l, x1 - m - l, x2 - m - l, x3 - m - l);
    }
}

// ---------------- launch ----------------
extern "C" void kernel_launch(void* const* d_in, const int* in_sizes, int n_in,
                              void* d_out, int out_size) {
    const float* x      = (const float*)d_in[0];
    const float* W_in   = (const float*)d_in[1];
    const float* b_in   = (const float*)d_in[2];
    const float* W_ih   = (const float*)d_in[3];
    const float* b_ih   = (const float*)d_in[4];
    const float* W_hh   = (const float*)d_in[5];
    const float* b_hh   = (const float*)d_in[6];
    const float* w_time = (const float*)d_in[7];
    const float* W_br   = (const float*)d_in[8];
    const float* b_br   = (const float*)d_in[9];
    float* out = (float*)d_out;

    combine_kernel<<<GDIM, 128>>>(W_in, b_in, W_ih, b_ih, W_hh, b_hh);
    gemm_kernel<<<dim3(4, 1024), 256>>>(x);

    // gates(1024) + hb0/hb1(256) + Wsp(512*25 float2 = 25600 floats)
    size_t shmem = (size_t)(1024 + 256 + GDIM * WSTRIDE * 2) * sizeof(float);  // 107520 B
    cudaFuncSetAttribute(lstm_kernel, cudaFuncAttributeMaxDynamicSharedMemorySize, (int)shmem);
    lstm_kernel<<<BATCH / 2, 512, shmem>>>(w_time);

    logits_kernel<<<(BATCH * SEQ) / 8, 256>>>(W_br, b_br, out);
}